// round 17
// baseline (speedup 1.0000x reference)
#include <cuda_runtime.h>
#include <cuda_bf16.h>
#include <cuda_fp16.h>
#include <cstdint>
#include <math.h>

#define N_NODES 25000
#define M_PAD   25088            // 392 * 64
#define N_EDGES 100000
#define H 64
#define K2 4224                  // 4096 (P edge part) + 64 (h for roots) + 64 (Q for be3)
#define N_LAYERS 3

// ---------------- scratch (static device globals) ---------------------------
__device__ float g_h[N_NODES * H];
__device__ float g_hidden[N_NODES * H];
__device__ float g_ew2[N_EDGES * H];
__device__ __align__(128) __half g_P16[(size_t)M_PAD * K2];          // ~212 MB fp16
__device__ __align__(128) __half g_B16[H * K2];                      // Bt[n][k] fp16
__device__ __align__(128) __half g_Wih16[64 * 192];                  // WihT fp16 [i][j]
__device__ float g_gi[(size_t)N_NODES * 192];                        // GRU input gates
__device__ int   g_deg[N_NODES];
__device__ int   g_off[N_NODES + 1];
__device__ int   g_cur[N_NODES];
__device__ int   g_csr[N_EDGES];

// ---------------- helpers ------------------------------------------------
__device__ __forceinline__ uint32_t smem_u32(const void* p) {
    uint32_t a;
    asm("{ .reg .u64 t; cvta.to.shared.u64 t, %1; cvt.u32.u64 %0, t; }" : "=r"(a) : "l"(p));
    return a;
}

__device__ __forceinline__ void mma16816h(float* c, const uint32_t* a, uint32_t b0, uint32_t b1) {
    asm volatile("mma.sync.aligned.m16n8k16.row.col.f32.f16.f16.f32 "
        "{%0,%1,%2,%3}, {%4,%5,%6,%7}, {%8,%9}, {%0,%1,%2,%3};"
        : "+f"(c[0]), "+f"(c[1]), "+f"(c[2]), "+f"(c[3])
        : "r"(a[0]), "r"(a[1]), "r"(a[2]), "r"(a[3]), "r"(b0), "r"(b1));
}

__device__ __forceinline__ void ldsm_x4(uint32_t* r, uint32_t addr) {
    asm volatile("ldmatrix.sync.aligned.m8n8.x4.shared.b16 {%0,%1,%2,%3}, [%4];"
        : "=r"(r[0]), "=r"(r[1]), "=r"(r[2]), "=r"(r[3]) : "r"(addr));
}

// ---------------- zero init --------------------------------------------------
__global__ void k_zero_misc() {
    int i = blockIdx.x * blockDim.x + threadIdx.x;
    int st = gridDim.x * blockDim.x;
    for (int idx = i; idx < N_NODES; idx += st) g_deg[idx] = 0;
    for (int idx = i; idx < N_NODES * H; idx += st) g_hidden[idx] = 0.f;
    const size_t padN = (size_t)(M_PAD - N_NODES) * K2;
    __half z = __float2half_rn(0.f);
    for (size_t idx = i; idx < padN; idx += st)
        g_P16[(size_t)N_NODES * K2 + idx] = z;
}

// ---------------- node MLP (register-blocked 4x4, tile=64 nodes) --------------
#define NMLP_SMEM ((2048 + 4096 + 4096 + 192 + 32 * 68 + 64 * 68 + 64 * 68) * 4)
__global__ void __launch_bounds__(256) k_node_mlp(const float* __restrict__ x,
                           const float* __restrict__ W1, const float* __restrict__ b1,
                           const float* __restrict__ W2, const float* __restrict__ b2,
                           const float* __restrict__ W3, const float* __restrict__ b3) {
    extern __shared__ float sm[];
    float* W1T = sm;
    float* W2T = W1T + 2048;
    float* W3T = W2T + 4096;
    float* b1s = W3T + 4096;
    float* b2s = b1s + 64;
    float* b3s = b2s + 64;
    float* xT  = b3s + 64;
    float* h1T = xT + 32 * 68;
    float* h2T = h1T + 64 * 68;
    int tid = threadIdx.x;
    for (int i = tid; i < 2048; i += 256) { int o = i >> 5, j = i & 31; W1T[j * 64 + o] = W1[i]; }
    for (int i = tid; i < 4096; i += 256) { int o = i >> 6, j = i & 63; W2T[j * 64 + o] = W2[i]; W3T[j * 64 + o] = W3[i]; }
    if (tid < 64) { b1s[tid] = b1[tid]; b2s[tid] = b2[tid]; b3s[tid] = b3[tid]; }
    int n0 = blockIdx.x * 64;
    #pragma unroll
    for (int q = 0; q < 2; q++) {
        int idx = q * 256 + tid;
        int n = idx >> 3, j = (idx & 7) * 4;
        float4 v = make_float4(0.f, 0.f, 0.f, 0.f);
        if (n0 + n < N_NODES) v = *(const float4*)(x + (size_t)(n0 + n) * 32 + j);
        xT[(j + 0) * 68 + n] = v.x;
        xT[(j + 1) * 68 + n] = v.y;
        xT[(j + 2) * 68 + n] = v.z;
        xT[(j + 3) * 68 + n] = v.w;
    }
    __syncthreads();
    int ng = (tid & 15) * 4;
    int og = (tid >> 4) * 4;
    float acc[4][4];
    #pragma unroll
    for (int ni = 0; ni < 4; ni++)
        #pragma unroll
        for (int oi = 0; oi < 4; oi++) acc[ni][oi] = b1s[og + oi];
    for (int j = 0; j < 32; j++) {
        float4 wv = *(const float4*)&W1T[j * 64 + og];
        float4 ev = *(const float4*)&xT[j * 68 + ng];
        float e[4] = {ev.x, ev.y, ev.z, ev.w};
        float wl[4] = {wv.x, wv.y, wv.z, wv.w};
        #pragma unroll
        for (int ni = 0; ni < 4; ni++)
            #pragma unroll
            for (int oi = 0; oi < 4; oi++) acc[ni][oi] += e[ni] * wl[oi];
    }
    #pragma unroll
    for (int oi = 0; oi < 4; oi++) {
        float4 v = make_float4(fmaxf(acc[0][oi], 0.f), fmaxf(acc[1][oi], 0.f),
                               fmaxf(acc[2][oi], 0.f), fmaxf(acc[3][oi], 0.f));
        *(float4*)&h1T[(og + oi) * 68 + ng] = v;
    }
    __syncthreads();
    #pragma unroll
    for (int ni = 0; ni < 4; ni++)
        #pragma unroll
        for (int oi = 0; oi < 4; oi++) acc[ni][oi] = b2s[og + oi];
    for (int j = 0; j < 64; j++) {
        float4 wv = *(const float4*)&W2T[j * 64 + og];
        float4 ev = *(const float4*)&h1T[j * 68 + ng];
        float e[4] = {ev.x, ev.y, ev.z, ev.w};
        float wl[4] = {wv.x, wv.y, wv.z, wv.w};
        #pragma unroll
        for (int ni = 0; ni < 4; ni++)
            #pragma unroll
            for (int oi = 0; oi < 4; oi++) acc[ni][oi] += e[ni] * wl[oi];
    }
    #pragma unroll
    for (int oi = 0; oi < 4; oi++) {
        float4 v = make_float4(fmaxf(acc[0][oi], 0.f), fmaxf(acc[1][oi], 0.f),
                               fmaxf(acc[2][oi], 0.f), fmaxf(acc[3][oi], 0.f));
        *(float4*)&h2T[(og + oi) * 68 + ng] = v;
    }
    __syncthreads();
    #pragma unroll
    for (int ni = 0; ni < 4; ni++)
        #pragma unroll
        for (int oi = 0; oi < 4; oi++) acc[ni][oi] = b3s[og + oi];
    for (int j = 0; j < 64; j++) {
        float4 wv = *(const float4*)&W3T[j * 64 + og];
        float4 ev = *(const float4*)&h2T[j * 68 + ng];
        float e[4] = {ev.x, ev.y, ev.z, ev.w};
        float wl[4] = {wv.x, wv.y, wv.z, wv.w};
        #pragma unroll
        for (int ni = 0; ni < 4; ni++)
            #pragma unroll
            for (int oi = 0; oi < 4; oi++) acc[ni][oi] += e[ni] * wl[oi];
    }
    #pragma unroll
    for (int ni = 0; ni < 4; ni++) {
        int node = n0 + ng + ni;
        if (node < N_NODES)
            *(float4*)&g_h[(size_t)node * 64 + og] =
                make_float4(acc[ni][0], acc[ni][1], acc[ni][2], acc[ni][3]);
    }
}

// ---------------- edge MLP (register-blocked 4x4, tile=64 edges) --------------
#define EMLP_SMEM ((1024 + 4096 + 128 + 16 * 68 + 64 * 68) * 4)
__global__ void __launch_bounds__(256) k_edge_mlp(const float* __restrict__ ea,
                           const float* __restrict__ W1, const float* __restrict__ b1,
                           const float* __restrict__ W2, const float* __restrict__ b2) {
    extern __shared__ float sm[];
    float* W1T = sm;
    float* W2T = W1T + 1024;
    float* b1s = W2T + 4096;
    float* b2s = b1s + 64;
    float* eaT = b2s + 64;
    float* h1T = eaT + 16 * 68;
    int tid = threadIdx.x;
    for (int i = tid; i < 1024; i += 256) { int o = i >> 4, j = i & 15; W1T[j * 64 + o] = W1[i]; }
    for (int i = tid; i < 4096; i += 256) { int o = i >> 6, j = i & 63; W2T[j * 64 + o] = W2[i]; }
    if (tid < 64) { b1s[tid] = b1[tid]; b2s[tid] = b2[tid]; }
    int e0 = blockIdx.x * 64;
    {
        int e = tid >> 2, j = (tid & 3) * 4;
        float4 v = make_float4(0.f, 0.f, 0.f, 0.f);
        if (e0 + e < N_EDGES) v = *(const float4*)(ea + (size_t)(e0 + e) * 16 + j);
        eaT[(j + 0) * 68 + e] = v.x;
        eaT[(j + 1) * 68 + e] = v.y;
        eaT[(j + 2) * 68 + e] = v.z;
        eaT[(j + 3) * 68 + e] = v.w;
    }
    __syncthreads();
    int eg = (tid & 15) * 4;
    int og = (tid >> 4) * 4;
    float acc[4][4];
    #pragma unroll
    for (int ei = 0; ei < 4; ei++)
        #pragma unroll
        for (int oi = 0; oi < 4; oi++) acc[ei][oi] = b1s[og + oi];
    #pragma unroll
    for (int j = 0; j < 16; j++) {
        float4 wv = *(const float4*)&W1T[j * 64 + og];
        float4 ev = *(const float4*)&eaT[j * 68 + eg];
        float e[4] = {ev.x, ev.y, ev.z, ev.w};
        float wl[4] = {wv.x, wv.y, wv.z, wv.w};
        #pragma unroll
        for (int ei = 0; ei < 4; ei++)
            #pragma unroll
            for (int oi = 0; oi < 4; oi++) acc[ei][oi] += e[ei] * wl[oi];
    }
    #pragma unroll
    for (int oi = 0; oi < 4; oi++) {
        float4 v = make_float4(fmaxf(acc[0][oi], 0.f), fmaxf(acc[1][oi], 0.f),
                               fmaxf(acc[2][oi], 0.f), fmaxf(acc[3][oi], 0.f));
        *(float4*)&h1T[(og + oi) * 68 + eg] = v;
    }
    __syncthreads();
    #pragma unroll
    for (int ei = 0; ei < 4; ei++)
        #pragma unroll
        for (int oi = 0; oi < 4; oi++) acc[ei][oi] = b2s[og + oi];
    for (int j = 0; j < 64; j++) {
        float4 wv = *(const float4*)&W2T[j * 64 + og];
        float4 ev = *(const float4*)&h1T[j * 68 + eg];
        float e[4] = {ev.x, ev.y, ev.z, ev.w};
        float wl[4] = {wv.x, wv.y, wv.z, wv.w};
        #pragma unroll
        for (int ei = 0; ei < 4; ei++)
            #pragma unroll
            for (int oi = 0; oi < 4; oi++) acc[ei][oi] += e[ei] * wl[oi];
    }
    #pragma unroll
    for (int ei = 0; ei < 4; ei++) {
        int e = e0 + eg + ei;
        if (e < N_EDGES)
            *(float4*)&g_ew2[(size_t)e * 64 + og] =
                make_float4(fmaxf(acc[ei][0], 0.f), fmaxf(acc[ei][1], 0.f),
                            fmaxf(acc[ei][2], 0.f), fmaxf(acc[ei][3], 0.f));
    }
}

// ---------------- CSR build --------------------------------------------------
__global__ void k_hist(const int* __restrict__ ei) {
    int i = blockIdx.x * blockDim.x + threadIdx.x, st = gridDim.x * blockDim.x;
    for (int e = i; e < N_EDGES; e += st) atomicAdd(&g_deg[ei[N_EDGES + e]], 1);
}

__global__ void k_scan() {
    __shared__ int part[1024];
    int t = threadIdx.x;
    const int CH = (N_NODES + 1023) / 1024;
    int b0 = t * CH, b1 = min(b0 + CH, N_NODES);
    int s = 0;
    for (int i = b0; i < b1; i++) s += g_deg[i];
    part[t] = s;
    __syncthreads();
    for (int d = 1; d < 1024; d <<= 1) {
        int v = (t >= d) ? part[t - d] : 0;
        __syncthreads();
        part[t] += v;
        __syncthreads();
    }
    int run = (t == 0) ? 0 : part[t - 1];
    for (int i = b0; i < b1; i++) { g_off[i] = run; g_cur[i] = run; run += g_deg[i]; }
    if (t == 1023) g_off[N_NODES] = part[1023];
}

__global__ void k_fill(const int* __restrict__ ei) {
    int i = blockIdx.x * blockDim.x + threadIdx.x, st = gridDim.x * blockDim.x;
    for (int e = i; e < N_EDGES; e += st) {
        int d = ei[N_EDGES + e];
        int p = atomicAdd(&g_cur[d], 1);
        g_csr[p] = e;
    }
}

__global__ void k_sort() {
    int d = blockIdx.x * blockDim.x + threadIdx.x;
    if (d >= N_NODES) return;
    int a = g_off[d], b = g_off[d + 1];
    for (int i = a + 1; i < b; i++) {
        int v = g_csr[i];
        int j = i - 1;
        while (j >= a && g_csr[j] > v) { g_csr[j + 1] = g_csr[j]; j--; }
        g_csr[j + 1] = v;
    }
}

// ---------------- build Bt fp16 static + Wih fp16 (once) ----------------------
__global__ void k_buildB_static(const float* __restrict__ We3, const float* __restrict__ be3,
                                const float* __restrict__ Wih) {
    int i0 = blockIdx.x * blockDim.x + threadIdx.x, st = gridDim.x * blockDim.x;
    for (int idx = i0; idx < H * K2; idx += st) {
        int n = idx / K2, kg = idx % K2;
        if (kg >= 4096 && kg < 4160) continue;
        float v;
        if (kg < 4096) { int i = kg >> 6, k = kg & 63; v = We3[((i << 6) + n) * 64 + k]; }
        else           { v = be3[((kg - 4160) << 6) + n]; }
        g_B16[idx] = __float2half_rn(v);
    }
    for (int idx = i0; idx < 64 * 192; idx += st) {
        int i = idx / 192, j = idx % 192;
        g_Wih16[idx] = __float2half_rn(Wih[j * 64 + i]);
    }
}

__global__ void k_buildB_roots(const float* __restrict__ roots, int l) {
    int idx = blockIdx.x * blockDim.x + threadIdx.x;
    if (idx >= 64 * 64) return;
    int n = idx >> 6, r = idx & 63;
    g_B16[n * K2 + 4096 + r] = __float2half_rn(roots[(l * 64 + r) * 64 + n]);
}

// ---------------- build P rows (row-per-lane, vectorized fp16 stores) ---------
__global__ void __launch_bounds__(128) k_buildP(const int* __restrict__ ei) {
    int tid = threadIdx.x, warp = tid >> 5, lane = tid & 31;
    int d = blockIdx.x * 2 + (warp >> 1);
    int r = (warp & 1) * 32 + lane;            // h-row 0..63

    float acc[64];
    #pragma unroll
    for (int k = 0; k < 64; k++) acc[k] = 0.f;

    int off0 = g_off[d];
    int deg = g_off[d + 1] - off0;
    for (int j = 0; j < deg; j++) {
        int e = g_csr[off0 + j];               // sorted -> deterministic order
        int s = ei[e];
        float hv = g_h[(size_t)s * 64 + r];    // coalesced across lanes
        const float4* ew4 = (const float4*)(g_ew2 + (size_t)e * 64);
        #pragma unroll
        for (int q = 0; q < 16; q++) {
            float4 w = ew4[q];                 // broadcast
            acc[q * 4 + 0] += hv * w.x;
            acc[q * 4 + 1] += hv * w.y;
            acc[q * 4 + 2] += hv * w.z;
            acc[q * 4 + 3] += hv * w.w;
        }
    }
    // store row r (64 halves) vectorized: 8 x STG.128
    size_t rb = (size_t)d * K2 + (size_t)r * 64;
    #pragma unroll
    for (int q8 = 0; q8 < 8; q8++) {
        __half2 p0 = __float22half2_rn(make_float2(acc[q8 * 8 + 0], acc[q8 * 8 + 1]));
        __half2 p1 = __float22half2_rn(make_float2(acc[q8 * 8 + 2], acc[q8 * 8 + 3]));
        __half2 p2 = __float22half2_rn(make_float2(acc[q8 * 8 + 4], acc[q8 * 8 + 5]));
        __half2 p3 = __float22half2_rn(make_float2(acc[q8 * 8 + 6], acc[q8 * 8 + 7]));
        uint4 v;
        v.x = *(uint32_t*)&p0; v.y = *(uint32_t*)&p1;
        v.z = *(uint32_t*)&p2; v.w = *(uint32_t*)&p3;
        *(uint4*)(g_P16 + rb + q8 * 8) = v;
    }

    // tail rows: h (4096..4159) and Q (4160..4223)
    {
        int ns = tid >> 6, i = tid & 63;
        int dn = blockIdx.x * 2 + ns;
        size_t rb2 = (size_t)dn * K2;
        g_P16[rb2 + 4096 + i] = __float2half_rn(g_h[(size_t)dn * 64 + i]);
        int o0 = g_off[dn], dg = g_off[dn + 1] - o0;
        float q = 0.f;
        for (int j = 0; j < dg; j++) q += g_h[(size_t)ei[g_csr[o0 + j]] * 64 + i];
        g_P16[rb2 + 4160 + i] = __float2half_rn(q);
    }
}

// ---------------- GEMM (M64 fp16) + fused gi epilogue -------------------------
// smem: [0,40960) pipeline (4xA + 4xB stages); [40960,65536) WihT fp16.
// Epilogue reuses [0,17408) as mT_t (float, [col][node] stride 68).
#define NKB2 132                 // K2 / 32
#define A_STAGE 5120
#define B_OFF   20480
#define B_STAGE 5120
#define WIH_OFF 40960
#define GEMM_SMEM 65536

__device__ __forceinline__ void copy_stage(char* smb, int slot, int m0, int kb, int tid) {
    int row = tid >> 2, c4 = tid & 3;
    {
        const __half* src = g_P16 + (size_t)(m0 + row) * K2 + kb * 32 + c4 * 8;
        uint32_t dst = smem_u32(smb + slot * A_STAGE + row * 80 + c4 * 16);
        asm volatile("cp.async.cg.shared.global [%0], [%1], 16;" :: "r"(dst), "l"(src));
    }
    {
        const __half* src = g_B16 + (size_t)row * K2 + kb * 32 + c4 * 8;
        uint32_t dst = smem_u32(smb + B_OFF + slot * B_STAGE + row * 80 + c4 * 16);
        asm volatile("cp.async.cg.shared.global [%0], [%1], 16;" :: "r"(dst), "l"(src));
    }
    asm volatile("cp.async.commit_group;" ::: "memory");
}

__global__ void __launch_bounds__(256, 3) k_gemm_mma(const float* __restrict__ cbias,
                                                     const float* __restrict__ bih, int l) {
    extern __shared__ __align__(16) char smb[];
    const int tid = threadIdx.x, w = tid >> 5, lane = tid & 31;
    const int m0 = blockIdx.x * 64;
    const int lq = lane >> 2;
    const int lr = lane & 3;
    const int wm = w >> 1;
    const int wn = w & 1;

    const int l7 = lane & 7;
    const int lbit = (lane >> 3) & 1;
    const int csel = (lane >> 4) ? 16 : 0;
    const uint32_t aoff = (uint32_t)((wm * 16 + l7 + lbit * 8) * 80 + csel);
    uint32_t brow_off[2];
    #pragma unroll
    for (int g = 0; g < 2; g++)
        brow_off[g] = (uint32_t)((wn * 32 + g * 16 + l7 + lbit * 8) * 80 + csel);

    float acc[4][4];
    #pragma unroll
    for (int na = 0; na < 4; na++)
        #pragma unroll
        for (int v = 0; v < 4; v++) acc[na][v] = 0.f;

    // prefetch WihT (oldest cp.async group; FIFO completion keeps loop waits valid)
    #pragma unroll
    for (int q = 0; q < 6; q++) {
        int idx = q * 256 + tid;               // 1536 chunks of 16B
        const __half* src = g_Wih16 + idx * 8;
        uint32_t dst = smem_u32(smb + WIH_OFF + idx * 16);
        asm volatile("cp.async.cg.shared.global [%0], [%1], 16;" :: "r"(dst), "l"(src));
    }
    asm volatile("cp.async.commit_group;" ::: "memory");

    copy_stage(smb, 0, m0, 0, tid);
    copy_stage(smb, 1, m0, 1, tid);
    copy_stage(smb, 2, m0, 2, tid);

    uint32_t sb = smem_u32(smb);
    for (int blk = 0; blk < NKB2; blk++) {
        int rem = NKB2 - 1 - blk;
        if (rem >= 2)      asm volatile("cp.async.wait_group 2;" ::: "memory");
        else if (rem == 1) asm volatile("cp.async.wait_group 1;" ::: "memory");
        else               asm volatile("cp.async.wait_group 0;" ::: "memory");
        __syncthreads();

        uint32_t abase = sb + (blk & 3) * A_STAGE;
        uint32_t bbase = sb + B_OFF + (blk & 3) * B_STAGE;
        #pragma unroll
        for (int s = 0; s < 2; s++) {
            uint32_t k0b = (uint32_t)(s * 32);
            uint32_t af[4];
            ldsm_x4(af, abase + aoff + k0b);
            #pragma unroll
            for (int g = 0; g < 2; g++) {
                uint32_t bh[4];
                ldsm_x4(bh, bbase + brow_off[g] + k0b);
                mma16816h(acc[2 * g],     af, bh[0], bh[2]);
                mma16816h(acc[2 * g + 1], af, bh[1], bh[3]);
            }
        }
        if (blk + 3 < NKB2) copy_stage(smb, (blk + 3) & 3, m0, blk + 3, tid);
    }
    __syncthreads();                            // all reads of last stage done

    // stage m-tile (+cbias) transposed into [0,17408): mT[c][n] stride 68
    float* mT = (float*)smb;
    {
        int rl = wm * 16 + lq;                  // local rows rl, rl+8
        #pragma unroll
        for (int na = 0; na < 4; na++) {
            int c0 = wn * 32 + na * 8 + lr * 2;
            float bx = cbias[l * 64 + c0], by = cbias[l * 64 + c0 + 1];
            mT[c0 * 68 + rl]            = acc[na][0] + bx;
            mT[(c0 + 1) * 68 + rl]      = acc[na][1] + by;
            mT[c0 * 68 + rl + 8]        = acc[na][2] + bx;
            mT[(c0 + 1) * 68 + rl + 8]  = acc[na][3] + by;
        }
    }
    __syncthreads();

    // gi = m @ Wih^T + bih   (thread = 4 nodes x 12 gate-cols)
    const __half* WT = (const __half*)(smb + WIH_OFF);
    int ng = (tid & 15) * 4;
    int og = (tid >> 4) * 12;
    float gacc[4][12];
    #pragma unroll
    for (int oi = 0; oi < 12; oi++) {
        float b = bih[og + oi];
        #pragma unroll
        for (int ni = 0; ni < 4; ni++) gacc[ni][oi] = b;
    }
    for (int i = 0; i < 64; i++) {
        float4 mv = *(const float4*)&mT[i * 68 + ng];
        float m4[4] = {mv.x, mv.y, mv.z, mv.w};
        float wl[12];
        #pragma unroll
        for (int q = 0; q < 6; q++) {
            __half2 hp = *(const __half2*)&WT[i * 192 + og + q * 2];
            float2 f = __half22float2(hp);
            wl[q * 2] = f.x; wl[q * 2 + 1] = f.y;
        }
        #pragma unroll
        for (int ni = 0; ni < 4; ni++)
            #pragma unroll
            for (int oi = 0; oi < 12; oi++) gacc[ni][oi] += m4[ni] * wl[oi];
    }
    #pragma unroll
    for (int ni = 0; ni < 4; ni++) {
        int node = m0 + ng + ni;
        if (node < N_NODES) {
            #pragma unroll
            for (int q = 0; q < 3; q++)
                *(float4*)&g_gi[(size_t)node * 192 + og + q * 4] =
                    make_float4(gacc[ni][q * 4 + 0], gacc[ni][q * 4 + 1],
                                gacc[ni][q * 4 + 2], gacc[ni][q * 4 + 3]);
        }
    }
}

// ---------------- GRU part 2: gh + combine ------------------------------------
#define GCB_SMEM ((12288 + 192 + 64 * 68) * 4)
__global__ void __launch_bounds__(256) k_gru_comb(const float* __restrict__ Whh,
                                                  const float* __restrict__ bhh,
                                                  float* __restrict__ dout, int last) {
    extern __shared__ float sm[];
    float* WT   = sm;                // [i*192 + j]
    float* bhhs = WT + 12288;
    float* hT   = bhhs + 192;        // [i][n] stride 68
    int tid = threadIdx.x;
    for (int idx = tid; idx < 12288; idx += 256) {
        int j = idx >> 6, i = idx & 63;
        WT[i * 192 + j] = Whh[idx];
    }
    if (tid < 192) bhhs[tid] = bhh[tid];
    int n0 = blockIdx.x * 64;
    #pragma unroll
    for (int q = 0; q < 4; q++) {
        int idx = q * 256 + tid;
        int n = idx >> 4, c4 = (idx & 15) * 4;
        float4 v = make_float4(0.f, 0.f, 0.f, 0.f);
        if (n0 + n < N_NODES) v = *(const float4*)(g_hidden + (size_t)(n0 + n) * 64 + c4);
        hT[(c4 + 0) * 68 + n] = v.x;
        hT[(c4 + 1) * 68 + n] = v.y;
        hT[(c4 + 2) * 68 + n] = v.z;
        hT[(c4 + 3) * 68 + n] = v.w;
    }
    __syncthreads();
    int ng = (tid & 15) * 4;
    int cg = (tid >> 4) * 4;
    float ar[4][4], az[4][4], an[4][4];
    #pragma unroll
    for (int ni = 0; ni < 4; ni++)
        #pragma unroll
        for (int oi = 0; oi < 4; oi++) {
            ar[ni][oi] = bhhs[cg + oi];
            az[ni][oi] = bhhs[64 + cg + oi];
            an[ni][oi] = bhhs[128 + cg + oi];
        }
    for (int i = 0; i < 64; i++) {
        float4 hv = *(const float4*)&hT[i * 68 + ng];
        float h4[4] = {hv.x, hv.y, hv.z, hv.w};
        float4 wr = *(const float4*)&WT[i * 192 + cg];
        float4 wz = *(const float4*)&WT[i * 192 + 64 + cg];
        float4 wn = *(const float4*)&WT[i * 192 + 128 + cg];
        float wrl[4] = {wr.x, wr.y, wr.z, wr.w};
        float wzl[4] = {wz.x, wz.y, wz.z, wz.w};
        float wnl[4] = {wn.x, wn.y, wn.z, wn.w};
        #pragma unroll
        for (int ni = 0; ni < 4; ni++)
            #pragma unroll
            for (int oi = 0; oi < 4; oi++) {
                ar[ni][oi] += h4[ni] * wrl[oi];
                az[ni][oi] += h4[ni] * wzl[oi];
                an[ni][oi] += h4[ni] * wnl[oi];
            }
    }
    #pragma unroll
    for (int ni = 0; ni < 4; ni++) {
        int node = n0 + ng + ni;
        if (node >= N_NODES) continue;
        float4 gir = *(const float4*)&g_gi[(size_t)node * 192 + cg];
        float4 giz = *(const float4*)&g_gi[(size_t)node * 192 + 64 + cg];
        float4 gin = *(const float4*)&g_gi[(size_t)node * 192 + 128 + cg];
        float gr[4] = {gir.x, gir.y, gir.z, gir.w};
        float gz[4] = {giz.x, giz.y, giz.z, giz.w};
        float gn[4] = {gin.x, gin.y, gin.z, gin.w};
        float out[4];
        #pragma unroll
        for (int oi = 0; oi < 4; oi++) {
            float hid = hT[(cg + oi) * 68 + ng + ni];
            float r = 1.f / (1.f + expf(-(gr[oi] + ar[ni][oi])));
            float z = 1.f / (1.f + expf(-(gz[oi] + az[ni][oi])));
            float n = tanhf(gn[oi] + r * an[ni][oi]);
            out[oi] = (1.f - z) * n + z * hid;
        }
        float4 o4 = make_float4(out[0], out[1], out[2], out[3]);
        *(float4*)&g_hidden[(size_t)node * 64 + cg] = o4;
        *(float4*)&g_h[(size_t)node * 64 + cg] = o4;
        if (last) *(float4*)&dout[(size_t)node * 64 + cg] = o4;
    }
}

// ---------------- launcher ----------------------------------------------------
extern "C" void kernel_launch(void* const* d_in, const int* in_sizes, int n_in,
                              void* d_out, int out_size) {
    const float* x     = (const float*)d_in[0];
    const float* ea    = (const float*)d_in[1];
    const float* Wn1   = (const float*)d_in[2];
    const float* bn1   = (const float*)d_in[3];
    const float* Wn2   = (const float*)d_in[4];
    const float* bn2   = (const float*)d_in[5];
    const float* Wn3   = (const float*)d_in[6];
    const float* bn3   = (const float*)d_in[7];
    const float* We1   = (const float*)d_in[8];
    const float* be1   = (const float*)d_in[9];
    const float* We2   = (const float*)d_in[10];
    const float* be2   = (const float*)d_in[11];
    const float* We3   = (const float*)d_in[12];
    const float* be3   = (const float*)d_in[13];
    const float* roots = (const float*)d_in[14];
    const float* cbias = (const float*)d_in[15];
    const float* gWih  = (const float*)d_in[16];
    const float* gWhh  = (const float*)d_in[17];
    const float* gbih  = (const float*)d_in[18];
    const float* gbhh  = (const float*)d_in[19];
    const int*   ei    = (const int*)d_in[20];
    float* dout = (float*)d_out;

    cudaFuncSetAttribute(k_gemm_mma, cudaFuncAttributeMaxDynamicSharedMemorySize, GEMM_SMEM);
    cudaFuncSetAttribute(k_node_mlp, cudaFuncAttributeMaxDynamicSharedMemorySize, NMLP_SMEM);
    cudaFuncSetAttribute(k_edge_mlp, cudaFuncAttributeMaxDynamicSharedMemorySize, EMLP_SMEM);
    cudaFuncSetAttribute(k_gru_comb, cudaFuncAttributeMaxDynamicSharedMemorySize, GCB_SMEM);

    k_zero_misc<<<400, 256>>>();
    k_node_mlp<<<(N_NODES + 63) / 64, 256, NMLP_SMEM>>>(x, Wn1, bn1, Wn2, bn2, Wn3, bn3);
    k_edge_mlp<<<(N_EDGES + 63) / 64, 256, EMLP_SMEM>>>(ea, We1, be1, We2, be2);
    k_hist<<<200, 256>>>(ei);
    k_scan<<<1, 1024>>>();
    k_fill<<<200, 256>>>(ei);
    k_sort<<<(N_NODES + 255) / 256, 256>>>();
    k_buildB_static<<<264, 256>>>(We3, be3, gWih);

    for (int l = 0; l < N_LAYERS; l++) {
        k_buildB_roots<<<16, 256>>>(roots, l);
        k_buildP<<<N_NODES / 2, 128>>>(ei);
        k_gemm_mma<<<M_PAD / 64, 256, GEMM_SMEM>>>(cbias, gbih, l);
        k_gru_comb<<<(N_NODES + 63) / 64, 256, GCB_SMEM>>>(gWhh, gbhh, dout, l == N_LAYERS - 1);
    }
}